// round 11
// baseline (speedup 1.0000x reference)
#include <cuda_runtime.h>
#include <math.h>
#include <stdint.h>

// Problem constants (B=1)
#define S_LEN   2048
#define HID_DIM 3584
#define NH      28
#define NKV     4
#define NG      7        // NH / NKV
#define HD      128
#define BM      64
#define BN      64
#define NTHREADS 256

typedef unsigned long long u64;

// Scratch: RoPE'd Q (scaled by log2e/sqrt(128)) and K, layout [head][seq][dim]
__device__ float g_Q[(size_t)NH * S_LEN * HD];   // ~29.4 MB
__device__ float g_K[(size_t)NKV * S_LEN * HD];  // ~4.2 MB

// Single-MUFU exp2 (accurate exp2f is a multi-instruction libm path without
// -use_fast_math). ~2 ulp; ex2.approx(-inf) = 0 handles masked lanes.
__device__ __forceinline__ float ex2(float x) {
    float y;
    asm("ex2.approx.ftz.f32 %0, %1;" : "=f"(y) : "f"(x));
    return y;
}

// ---- packed f32x2 ops (Blackwell FFMA2 path; bit-exact per-half fp32) ----
__device__ __forceinline__ u64 pack2(float lo, float hi) {
    u64 r;
    asm("mov.b64 %0, {%1, %2};" : "=l"(r) : "f"(lo), "f"(hi));
    return r;
}
__device__ __forceinline__ void fma2(u64& d, u64 a, u64 b) {
    asm("fma.rn.f32x2 %0, %1, %2, %0;" : "+l"(d) : "l"(a), "l"(b));
}
__device__ __forceinline__ u64 mul2(u64 a, u64 b) {
    u64 r;
    asm("mul.rn.f32x2 %0, %1, %2;" : "=l"(r) : "l"(a), "l"(b));
    return r;
}
__device__ __forceinline__ float2 unpack2(u64 v) {
    float lo, hi;
    asm("mov.b64 {%0, %1}, %2;" : "=f"(lo), "=f"(hi) : "l"(v));
    return make_float2(lo, hi);
}

// ---------------------------------------------------------------------------
// RoPE: out[h][s][d]      = (x[d]*cos[d]   - x[d+64]*sin[d])   * scale
//       out[h][s][d+64]   = (x[d+64]*cos[d+64] + x[d]*sin[d+64]) * scale
// which==0 -> g_Q, which==1 -> g_K
// ---------------------------------------------------------------------------
__global__ void rope_kernel(const float* __restrict__ x,
                            const float* __restrict__ cosb,
                            const float* __restrict__ sinb,
                            int nheads, int row_stride, float scale, int which) {
    int idx = blockIdx.x * blockDim.x + threadIdx.x;
    int total = S_LEN * nheads * (HD / 2);
    if (idx >= total) return;
    int d = idx & 63;
    int h = (idx >> 6) % nheads;
    int s = idx / (64 * nheads);

    const float* xr = x + (size_t)s * row_stride + h * HD;
    float x1 = xr[d];
    float x2 = xr[d + 64];
    float c1 = cosb[s * HD + d];
    float s1 = sinb[s * HD + d];
    float c2 = cosb[s * HD + d + 64];
    float s2 = sinb[s * HD + d + 64];

    float o1 = (x1 * c1 - x2 * s1) * scale;
    float o2 = (x2 * c2 + x1 * s2) * scale;

    float* outb = which ? g_K : g_Q;
    float* orow = outb + ((size_t)h * S_LEN + s) * HD;
    orow[d]      = o1;
    orow[d + 64] = o2;
}

// ---------------------------------------------------------------------------
// Flash attention, fp32 SIMT with packed f32x2 FMA (FFMA2) in both GEMMs.
// Grid: NH * (S_LEN/BM) blocks; q-tiles reversed for causal wave balance.
// 256 threads as 16x16: tx = tid&15 (score cols), ty = tid>>4 (rows).
// Each thread: 4 score rows x 4 cols; O tile 4 rows x 8 cols (as 4 f32x2
// pairs; V float4 cols tx and 16+tx -> conflict-free).
// Q logits pre-scaled by log2e/sqrt(128) -> softmax via exp2.
// ---------------------------------------------------------------------------
__global__ __launch_bounds__(NTHREADS, 2)
void attn_kernel(const float* __restrict__ Vsrc, float* __restrict__ out) {
    extern __shared__ float smem[];
    float* Qs = smem;               // BM*HD
    float* Ks = Qs + BM * HD;       // BN*HD (float4-swizzled per row)
    float* Vs = Ks + BN * HD;       // BN*HD
    float* Ps = Vs + BN * HD;       // BM*BN
    float4* Qs4 = (float4*)Qs;
    float4* Ks4 = (float4*)Ks;
    float4* Vs4 = (float4*)Vs;
    float4* Ps4 = (float4*)Ps;

    const int tid = threadIdx.x;
    const int tx = tid & 15;
    const int ty = tid >> 4;
    const int lc = tid & 31;   // loader float4 column
    const int lr = tid >> 5;   // loader row (stride 8)

    const int qt = (S_LEN / BM - 1) - (int)(blockIdx.x & 31);
    const int h  = (int)(blockIdx.x >> 5);
    const int kh = h / NG;
    const int m0 = qt * BM;

    // Load Q tile (coalesced float4)
    const float4* Qg = (const float4*)(g_Q + ((size_t)h * S_LEN + m0) * HD);
    #pragma unroll
    for (int rr = 0; rr < BM; rr += 8)
        Qs4[(rr + lr) * 32 + lc] = Qg[(size_t)(rr + lr) * 32 + lc];

    const float NEG_INF = __int_as_float(0xff800000);
    float m_i[4], l_i[4];
    u64 o2[4][4];                   // O accumulators: 4 rows x 4 f32x2 pairs
    #pragma unroll
    for (int i = 0; i < 4; i++) {
        m_i[i] = NEG_INF;
        l_i[i] = 0.f;
        #pragma unroll
        for (int c = 0; c < 4; c++) o2[i][c] = 0ull;  // (0.0f, 0.0f)
    }

    const float4* Kg = (const float4*)(g_K + (size_t)kh * S_LEN * HD);
    const float4* Vg = (const float4*)Vsrc;  // [s][128 float4s], head at +kh*32

    const int ntiles = qt + 1;
    for (int t = 0; t < ntiles; t++) {
        const int n0 = t * BN;

        // Load K (swizzled: col' = (c + (n>>2)) & 31 -> conflict-free strided
        // reads in the S-gemm) and V tiles.
        #pragma unroll
        for (int rr = 0; rr < BN; rr += 8) {
            int n = rr + lr;
            float4 kv = Kg[(size_t)(n0 + n) * 32 + lc];
            Ks4[n * 32 + ((lc + (n >> 2)) & 31)] = kv;
            Vs4[n * 32 + lc] = Vg[(size_t)(n0 + n) * 128 + kh * 32 + lc];
        }
        __syncthreads();

        // S = Q K^T, packed along the head-dim: acc2[i][j] holds
        // (even-K partial, odd-K partial); horizontal add at the end.
        u64 acc2[4][4];
        #pragma unroll
        for (int i = 0; i < 4; i++)
            #pragma unroll
            for (int j = 0; j < 4; j++) acc2[i][j] = 0ull;

        #pragma unroll 4
        for (int dc = 0; dc < 32; dc++) {
            u64 qp[4][2], kp[4][2];
            #pragma unroll
            for (int i = 0; i < 4; i++) {
                float4 q4 = Qs4[(4 * ty + i) * 32 + dc];
                qp[i][0] = pack2(q4.x, q4.y);
                qp[i][1] = pack2(q4.z, q4.w);
            }
            #pragma unroll
            for (int j = 0; j < 4; j++) {
                float4 k4 = Ks4[(4 * tx + j) * 32 + ((dc + tx) & 31)];
                kp[j][0] = pack2(k4.x, k4.y);
                kp[j][1] = pack2(k4.z, k4.w);
            }
            #pragma unroll
            for (int i = 0; i < 4; i++)
                #pragma unroll
                for (int j = 0; j < 4; j++) {
                    fma2(acc2[i][j], qp[i][0], kp[j][0]);
                    fma2(acc2[i][j], qp[i][1], kp[j][1]);
                }
        }

        // Online softmax update (per-row stats shared across the 16 tx lanes
        // via width-16 xor shuffles).
        const bool diag = (t == qt);
        #pragma unroll
        for (int i = 0; i < 4; i++) {
            float acc[4];
            #pragma unroll
            for (int j = 0; j < 4; j++) {
                float2 p = unpack2(acc2[i][j]);
                acc[j] = p.x + p.y;
            }
            if (diag) {
                const int mrow = m0 + 4 * ty + i;
                #pragma unroll
                for (int j = 0; j < 4; j++)
                    if (n0 + 4 * tx + j > mrow) acc[j] = NEG_INF;
            }
            float mx = fmaxf(fmaxf(acc[0], acc[1]), fmaxf(acc[2], acc[3]));
            mx = fmaxf(mx, __shfl_xor_sync(0xffffffffu, mx, 8, 16));
            mx = fmaxf(mx, __shfl_xor_sync(0xffffffffu, mx, 4, 16));
            mx = fmaxf(mx, __shfl_xor_sync(0xffffffffu, mx, 2, 16));
            mx = fmaxf(mx, __shfl_xor_sync(0xffffffffu, mx, 1, 16));
            float nm = fmaxf(m_i[i], mx);
            float sc = ex2(m_i[i] - nm);
            m_i[i] = nm;
            float p0 = ex2(acc[0] - nm);
            float p1 = ex2(acc[1] - nm);
            float p2 = ex2(acc[2] - nm);
            float p3 = ex2(acc[3] - nm);
            float rs = (p0 + p1) + (p2 + p3);
            rs += __shfl_xor_sync(0xffffffffu, rs, 8, 16);
            rs += __shfl_xor_sync(0xffffffffu, rs, 4, 16);
            rs += __shfl_xor_sync(0xffffffffu, rs, 2, 16);
            rs += __shfl_xor_sync(0xffffffffu, rs, 1, 16);
            l_i[i] = l_i[i] * sc + rs;
            u64 sc2 = pack2(sc, sc);
            #pragma unroll
            for (int c = 0; c < 4; c++) o2[i][c] = mul2(o2[i][c], sc2);
            Ps4[(4 * ty + i) * 16 + tx] = make_float4(p0, p1, p2, p3);
        }
        __syncthreads();

        // O += P V  (packed pairs along head-dim; V reads: float4 cols tx
        // and 16+tx -> conflict-free)
        #pragma unroll 2
        for (int nb = 0; nb < 16; nb++) {
            float pr[4][4];
            #pragma unroll
            for (int i = 0; i < 4; i++) {
                float4 p4 = Ps4[(4 * ty + i) * 16 + nb];
                pr[i][0] = p4.x; pr[i][1] = p4.y;
                pr[i][2] = p4.z; pr[i][3] = p4.w;
            }
            #pragma unroll
            for (int nn = 0; nn < 4; nn++) {
                float4 va = Vs4[(nb * 4 + nn) * 32 + tx];
                float4 vb = Vs4[(nb * 4 + nn) * 32 + 16 + tx];
                u64 vp0 = pack2(va.x, va.y);
                u64 vp1 = pack2(va.z, va.w);
                u64 vp2 = pack2(vb.x, vb.y);
                u64 vp3 = pack2(vb.z, vb.w);
                #pragma unroll
                for (int i = 0; i < 4; i++) {
                    u64 pn2 = pack2(pr[i][nn], pr[i][nn]);
                    fma2(o2[i][0], pn2, vp0);
                    fma2(o2[i][1], pn2, vp1);
                    fma2(o2[i][2], pn2, vp2);
                    fma2(o2[i][3], pn2, vp3);
                }
            }
        }
        __syncthreads();
    }

    // Epilogue: normalize and store to [s][h*128 + d].
    // Thread owns head-dim floats [4*tx, 4*tx+4) and [64+4*tx, 64+4*tx+4).
    float* outp = out + (size_t)m0 * HID_DIM + h * HD;
    #pragma unroll
    for (int i = 0; i < 4; i++) {
        float inv = 1.0f / l_i[i];
        int r = 4 * ty + i;
        float2 c0 = unpack2(o2[i][0]);
        float2 c1 = unpack2(o2[i][1]);
        float2 c2 = unpack2(o2[i][2]);
        float2 c3 = unpack2(o2[i][3]);
        float4 a = make_float4(c0.x * inv, c0.y * inv, c1.x * inv, c1.y * inv);
        float4 b = make_float4(c2.x * inv, c2.y * inv, c3.x * inv, c3.y * inv);
        *(float4*)(outp + (size_t)r * HID_DIM + 4 * tx)      = a;
        *(float4*)(outp + (size_t)r * HID_DIM + 64 + 4 * tx) = b;
    }
}

// ---------------------------------------------------------------------------
// Inputs (metadata order): query_states, key_states, value_states, cos, sin,
// attention_mask (unused: mask is exactly causal; we mask analytically).
// ---------------------------------------------------------------------------
extern "C" void kernel_launch(void* const* d_in, const int* in_sizes, int n_in,
                              void* d_out, int out_size) {
    (void)in_sizes; (void)n_in; (void)out_size;
    const float* q    = (const float*)d_in[0];
    const float* k    = (const float*)d_in[1];
    const float* v    = (const float*)d_in[2];
    const float* cosb = (const float*)d_in[3];
    const float* sinb = (const float*)d_in[4];
    float* out = (float*)d_out;

    // Fold 1/sqrt(HD) and the exp->exp2 conversion (log2 e) into Q.
    const float qscale = 1.4426950408889634f / sqrtf((float)HD);

    int totq = S_LEN * NH  * (HD / 2);
    int totk = S_LEN * NKV * (HD / 2);
    rope_kernel<<<(totq + NTHREADS - 1) / NTHREADS, NTHREADS>>>(
        q, cosb, sinb, NH, HID_DIM, qscale, 0);
    rope_kernel<<<(totk + NTHREADS - 1) / NTHREADS, NTHREADS>>>(
        k, cosb, sinb, NKV, NKV * HD, 1.0f, 1);

    const int smem_bytes = (BM * HD + 2 * BN * HD + BM * BN) * (int)sizeof(float); // 112 KB
    cudaFuncSetAttribute(attn_kernel,
                         cudaFuncAttributeMaxDynamicSharedMemorySize, smem_bytes);
    attn_kernel<<<NH * (S_LEN / BM), NTHREADS, smem_bytes>>>(v, out);
}

// round 15
// speedup vs baseline: 2.8918x; 2.8918x over previous
#include <cuda_runtime.h>
#include <math.h>
#include <stdint.h>

#define S_LEN   2048
#define HID_DIM 3584
#define NH      28
#define NKV     4
#define NG      7
#define HD      128
#define BM      128
#define BN      64
#define NT      256
#define QT_N    (S_LEN/BM)   // 16

// tf32-rounded scratch, layout [head][seq][dim]
__device__ float g_Q[(size_t)NH  * S_LEN * HD];
__device__ float g_K[(size_t)NKV * S_LEN * HD];
__device__ float g_V[(size_t)NKV * S_LEN * HD];

__device__ __forceinline__ float ex2(float x) {
    float y; asm("ex2.approx.ftz.f32 %0, %1;" : "=f"(y) : "f"(x)); return y;
}
__device__ __forceinline__ float tf32r(float x) {   // round-to-nearest tf32
    uint32_t y; asm("cvt.rna.tf32.f32 %0, %1;" : "=r"(y) : "f"(x));
    return __uint_as_float(y);
}
__device__ __forceinline__ uint32_t s2u(const void* p) {
    uint32_t a;
    asm("{ .reg .u64 t; cvta.to.shared.u64 t, %1; cvt.u32.u64 %0, t; }"
        : "=r"(a) : "l"(p));
    return a;
}
__device__ __forceinline__ void cp16(uint32_t dst, const void* src) {
    asm volatile("cp.async.cg.shared.global [%0], [%1], 16;" :: "r"(dst), "l"(src));
}
__device__ __forceinline__ void cp_commit() { asm volatile("cp.async.commit_group;"); }
__device__ __forceinline__ void cp_wait0()  { asm volatile("cp.async.wait_group 0;" ::: "memory"); }
__device__ __forceinline__ void cp_wait1()  { asm volatile("cp.async.wait_group 1;" ::: "memory"); }

__device__ __forceinline__ void mma8(float* c, uint32_t a0, uint32_t a1,
                                     uint32_t a2, uint32_t a3,
                                     uint32_t b0, uint32_t b1) {
    asm("mma.sync.aligned.m16n8k8.row.col.f32.tf32.tf32.f32 "
        "{%0,%1,%2,%3},{%4,%5,%6,%7},{%8,%9},{%0,%1,%2,%3};"
        : "+f"(c[0]), "+f"(c[1]), "+f"(c[2]), "+f"(c[3])
        : "r"(a0), "r"(a1), "r"(a2), "r"(a3), "r"(b0), "r"(b1));
}

// ---------------------------------------------------------------------------
// RoPE -> tf32 scratch. which==0 -> g_Q (scaled by log2e/sqrt(HD)), 1 -> g_K.
// ---------------------------------------------------------------------------
__global__ void rope_kernel(const float* __restrict__ x,
                            const float* __restrict__ cosb,
                            const float* __restrict__ sinb,
                            int nheads, int row_stride, float scale, int which) {
    int idx = blockIdx.x * blockDim.x + threadIdx.x;
    if (idx >= S_LEN * nheads * 64) return;
    int d = idx & 63, h = (idx >> 6) % nheads, s = idx / (64 * nheads);
    const float* xr = x + (size_t)s * row_stride + h * HD;
    float x1 = xr[d], x2 = xr[d + 64];
    float o1 = (x1 * cosb[s*HD+d]    - x2 * sinb[s*HD+d])    * scale;
    float o2 = (x2 * cosb[s*HD+d+64] + x1 * sinb[s*HD+d+64]) * scale;
    float* orow = (which ? g_K : g_Q) + ((size_t)h * S_LEN + s) * HD;
    orow[d]      = tf32r(o1);
    orow[d + 64] = tf32r(o2);
}

// V [s][kv*128] -> g_V[kh][s][d], tf32-rounded
__global__ void vconv_kernel(const float* __restrict__ v) {
    int idx = blockIdx.x * blockDim.x + threadIdx.x;
    if (idx >= NKV * S_LEN * HD) return;
    int d = idx & 127, kh = (idx >> 7) & 3, s = idx >> 9;
    g_V[((size_t)kh * S_LEN + s) * HD + d] = tf32r(v[idx]);
}

// ---------------------------------------------------------------------------
// Flash attention via tf32 mma.sync.m16n8k8. 8 warps; warp w owns q-rows
// R..R+15. Strides: Q/K 132 (≡4 mod 32), V 136 (≡8), P 68 — fragment
// LDS patterns conflict-free. Single-buffer K/V with cp.async cross-overlap.
// ---------------------------------------------------------------------------
__global__ __launch_bounds__(NT, 1)
void attn_mma(float* __restrict__ out) {
    extern __shared__ float sm[];
    float* Qs = sm;                      // 128 x stride 132
    float* Ks = Qs + 128 * 132;          // 64 x stride 132
    float* Vs = Ks + 64 * 132;           // 64 x stride 136
    float* Ps = Vs + 64 * 136;           // 128 x stride 68

    const int tid = threadIdx.x, lane = tid & 31, w = tid >> 5;
    const int qt = (QT_N - 1) - (int)(blockIdx.x & 15);
    const int h  = (int)(blockIdx.x >> 4), kh = h / NG;
    const int m0 = qt * BM, R = 16 * w;
    const int r0 = lane >> 2, cq = lane & 3;
    const int nt = 2 * qt + 2;

    const float* Kg = g_K + (size_t)kh * S_LEN * HD;
    const float* Vg = g_V + (size_t)kh * S_LEN * HD;
    const uint32_t ks_u = s2u(Ks), vs_u = s2u(Vs);

    // Q tile: coalesced float4 -> padded smem
    {
        const float4* Qg = (const float4*)(g_Q + ((size_t)h * S_LEN + m0) * HD);
        #pragma unroll
        for (int i = 0; i < 16; i++) {
            int id = tid + NT * i, row = id >> 5, c = id & 31;
            *(float4*)&Qs[row * 132 + c * 4] = Qg[(size_t)row * 32 + c];
        }
    }
    // Prologue: K(0), V(0)
    #pragma unroll
    for (int i = 0; i < 8; i++) {
        int id = tid + NT * i, row = id >> 5, c = id & 31;
        cp16(ks_u + (row * 132 + c * 4) * 4, Kg + (size_t)row * HD + c * 4);
    }
    cp_commit();
    #pragma unroll
    for (int i = 0; i < 8; i++) {
        int id = tid + NT * i, row = id >> 5, c = id & 31;
        cp16(vs_u + (row * 136 + c * 4) * 4, Vg + (size_t)row * HD + c * 4);
    }
    cp_commit();
    cp_wait1();          // K(0) done; V(0) pending
    __syncthreads();

    const float NEG_INF = __int_as_float(0xff800000);
    float m0f = NEG_INF, m1f = NEG_INF, l0 = 0.f, l1 = 0.f;
    float o[16][4];
    #pragma unroll
    for (int jn = 0; jn < 16; jn++)
        #pragma unroll
        for (int e = 0; e < 4; e++) o[jn][e] = 0.f;

    for (int t = 0; t < nt; t++) {
        const int n0 = t * BN;
        // ---- S = Q K^T ----
        float s[8][4];
        #pragma unroll
        for (int j = 0; j < 8; j++)
            #pragma unroll
            for (int e = 0; e < 4; e++) s[j][e] = 0.f;
        #pragma unroll 4
        for (int kk = 0; kk < 16; kk++) {
            int qoff = (R + r0) * 132 + kk * 8 + cq;
            uint32_t a0 = __float_as_uint(Qs[qoff]);
            uint32_t a1 = __float_as_uint(Qs[qoff + 8 * 132]);
            uint32_t a2 = __float_as_uint(Qs[qoff + 4]);
            uint32_t a3 = __float_as_uint(Qs[qoff + 8 * 132 + 4]);
            #pragma unroll
            for (int j = 0; j < 8; j++) {
                int koff = (j * 8 + r0) * 132 + kk * 8 + cq;
                mma8(s[j], a0, a1, a2, a3,
                     __float_as_uint(Ks[koff]), __float_as_uint(Ks[koff + 4]));
            }
        }
        // ---- mask (last 2 tiles) + online softmax (quad shuffles) ----
        const int row0 = m0 + R + r0, row1 = row0 + 8;
        if (t >= nt - 2) {
            #pragma unroll
            for (int j = 0; j < 8; j++) {
                int c0 = n0 + 8 * j + 2 * cq;
                if (c0     > row0) s[j][0] = NEG_INF;
                if (c0 + 1 > row0) s[j][1] = NEG_INF;
                if (c0     > row1) s[j][2] = NEG_INF;
                if (c0 + 1 > row1) s[j][3] = NEG_INF;
            }
        }
        float mx0 = NEG_INF, mx1 = NEG_INF;
        #pragma unroll
        for (int j = 0; j < 8; j++) {
            mx0 = fmaxf(mx0, fmaxf(s[j][0], s[j][1]));
            mx1 = fmaxf(mx1, fmaxf(s[j][2], s[j][3]));
        }
        mx0 = fmaxf(mx0, __shfl_xor_sync(0xffffffffu, mx0, 1));
        mx0 = fmaxf(mx0, __shfl_xor_sync(0xffffffffu, mx0, 2));
        mx1 = fmaxf(mx1, __shfl_xor_sync(0xffffffffu, mx1, 1));
        mx1 = fmaxf(mx1, __shfl_xor_sync(0xffffffffu, mx1, 2));
        float nm0 = fmaxf(m0f, mx0), nm1 = fmaxf(m1f, mx1);
        float sc0 = ex2(m0f - nm0), sc1 = ex2(m1f - nm1);
        m0f = nm0; m1f = nm1;
        float sum0 = 0.f, sum1 = 0.f;
        #pragma unroll
        for (int j = 0; j < 8; j++) {
            s[j][0] = ex2(s[j][0] - nm0); s[j][1] = ex2(s[j][1] - nm0);
            s[j][2] = ex2(s[j][2] - nm1); s[j][3] = ex2(s[j][3] - nm1);
            sum0 += s[j][0] + s[j][1];
            sum1 += s[j][2] + s[j][3];
        }
        sum0 += __shfl_xor_sync(0xffffffffu, sum0, 1);
        sum0 += __shfl_xor_sync(0xffffffffu, sum0, 2);
        sum1 += __shfl_xor_sync(0xffffffffu, sum1, 1);
        sum1 += __shfl_xor_sync(0xffffffffu, sum1, 2);
        l0 = l0 * sc0 + sum0;
        l1 = l1 * sc1 + sum1;
        #pragma unroll
        for (int jn = 0; jn < 16; jn++) {
            o[jn][0] *= sc0; o[jn][1] *= sc0;
            o[jn][2] *= sc1; o[jn][3] *= sc1;
        }
        // P write (warp-private rows; tf32-rounded)
        #pragma unroll
        for (int j = 0; j < 8; j++) {
            *(float2*)&Ps[(R + r0)     * 68 + 8 * j + 2 * cq] =
                make_float2(tf32r(s[j][0]), tf32r(s[j][1]));
            *(float2*)&Ps[(R + r0 + 8) * 68 + 8 * j + 2 * cq] =
                make_float2(tf32r(s[j][2]), tf32r(s[j][3]));
        }
        __syncthreads();                       // all warps done reading Ks
        if (t + 1 < nt) {                      // prefetch K(t+1)
            #pragma unroll
            for (int i = 0; i < 8; i++) {
                int id = tid + NT * i, row = id >> 5, c = id & 31;
                cp16(ks_u + (row * 132 + c * 4) * 4,
                     Kg + (size_t)(n0 + BN + row) * HD + c * 4);
            }
            cp_commit();
            cp_wait1();                        // V(t) done
        } else {
            cp_wait0();
        }
        __syncthreads();                       // V(t) visible
        // ---- O += P V ----
        #pragma unroll 2
        for (int kk = 0; kk < 8; kk++) {
            int poff = (R + r0) * 68 + kk * 8 + cq;
            uint32_t a0 = __float_as_uint(Ps[poff]);
            uint32_t a1 = __float_as_uint(Ps[poff + 8 * 68]);
            uint32_t a2 = __float_as_uint(Ps[poff + 4]);
            uint32_t a3 = __float_as_uint(Ps[poff + 8 * 68 + 4]);
            #pragma unroll
            for (int jn = 0; jn < 16; jn++) {
                int voff = (kk * 8 + cq) * 136 + jn * 8 + r0;
                mma8(o[jn], a0, a1, a2, a3,
                     __float_as_uint(Vs[voff]), __float_as_uint(Vs[voff + 4 * 136]));
            }
        }
        __syncthreads();                       // all warps done reading Vs
        if (t + 1 < nt) {                      // prefetch V(t+1)
            #pragma unroll
            for (int i = 0; i < 8; i++) {
                int id = tid + NT * i, row = id >> 5, c = id & 31;
                cp16(vs_u + (row * 136 + c * 4) * 4,
                     Vg + (size_t)(n0 + BN + row) * HD + c * 4);
            }
            cp_commit();
            cp_wait1();                        // K(t+1) done
            __syncthreads();                   // K(t+1) visible
        }
    }

    // ---- epilogue ----
    float inv0 = 1.0f / l0, inv1 = 1.0f / l1;
    float* op0 = out + (size_t)(m0 + R + r0)     * HID_DIM + h * HD;
    float* op1 = out + (size_t)(m0 + R + r0 + 8) * HID_DIM + h * HD;
    #pragma unroll
    for (int jn = 0; jn < 16; jn++) {
        *(float2*)&op0[8 * jn + 2 * cq] = make_float2(o[jn][0] * inv0, o[jn][1] * inv0);
        *(float2*)&op1[8 * jn + 2 * cq] = make_float2(o[jn][2] * inv1, o[jn][3] * inv1);
    }
}

// ---------------------------------------------------------------------------
extern "C" void kernel_launch(void* const* d_in, const int* in_sizes, int n_in,
                              void* d_out, int out_size) {
    (void)in_sizes; (void)n_in; (void)out_size;
    const float* q    = (const float*)d_in[0];
    const float* k    = (const float*)d_in[1];
    const float* v    = (const float*)d_in[2];
    const float* cosb = (const float*)d_in[3];
    const float* sinb = (const float*)d_in[4];
    float* out = (float*)d_out;

    const float qscale = 1.4426950408889634f / sqrtf((float)HD);
    int totq = S_LEN * NH * 64, totk = S_LEN * NKV * 64;
    rope_kernel<<<(totq + 255) / 256, 256>>>(q, cosb, sinb, NH, HID_DIM, qscale, 0);
    rope_kernel<<<(totk + 255) / 256, 256>>>(k, cosb, sinb, NKV, NKV * HD, 1.0f, 1);
    vconv_kernel<<<(NKV * S_LEN * HD + 255) / 256, 256>>>(v);

    const int smem_bytes = (128*132 + 64*132 + 64*136 + 128*68) * 4; // 171008
    cudaFuncSetAttribute(attn_mma,
                         cudaFuncAttributeMaxDynamicSharedMemorySize, smem_bytes);
    attn_mma<<<NH * QT_N, NT, smem_bytes>>>(out);
}